// round 3
// baseline (speedup 1.0000x reference)
#include <cuda_runtime.h>

// NAM: per-feature 1->H->H->1 MLPs.
// inputs (B,F), W1/b1 (F,H), W2 (F,H,H), b2 (F,H), W3 (F,H), b3 (F)
// outputs: out (B,) then fnn (B,F), concatenated in d_out.

#define F_  128
#define H_  64
#define BT  256   // batch rows per block
#define TPB 128   // threads per block (2 rows/thread)

__global__ __launch_bounds__(TPB) void nam_main_kernel(
    const float* __restrict__ inputs,
    const float* __restrict__ W1,
    const float* __restrict__ b1,
    const float* __restrict__ W2,
    const float* __restrict__ b2,
    const float* __restrict__ W3,
    const float* __restrict__ b3,
    float* __restrict__ fnn,
    int B)
{
    __shared__ float sW2[H_ * H_];          // W2[f]: row h contiguous in k
    __shared__ float sW1[H_], sb1[H_], sb2[H_], sW3[H_];

    const int f    = blockIdx.y;
    const int base = blockIdx.x * BT;
    const int t    = threadIdx.x;

    // Stage W2[f] (16KB) via float4, coalesced.
    {
        const float4* gW2v = (const float4*)(W2 + (size_t)f * H_ * H_);
        float4* sW2v = (float4*)sW2;
        #pragma unroll
        for (int i = 0; i < (H_ * H_ / 4) / TPB; i++)   // 1024/128 = 8
            sW2v[t + i * TPB] = gW2v[t + i * TPB];
    }
    if (t < H_) {
        sW1[t] = W1[f * H_ + t];
        sb1[t] = b1[f * H_ + t];
        sb2[t] = b2[f * H_ + t];
        sW3[t] = W3[f * H_ + t];
    }
    __syncthreads();

    const int r0 = base + t;
    const int r1 = base + t + TPB;
    const bool v0 = (r0 < B);
    const bool v1 = (r1 < B);

    const float x0 = v0 ? inputs[(size_t)r0 * F_ + f] : 0.0f;
    const float x1 = v1 ? inputs[(size_t)r1 * F_ + f] : 0.0f;

    float acc0[H_], acc1[H_];
    #pragma unroll
    for (int k = 0; k < H_; k++) {
        float bv = sb2[k];
        acc0[k] = bv;
        acc1[k] = bv;
    }

    // Hidden->hidden: h rolled, k fully unrolled (regs), broadcast LDS.128.
    for (int h = 0; h < H_; h++) {
        const float w1v = sW1[h];
        const float b1v = sb1[h];
        const float h10 = fmaxf(fmaf(x0, w1v, b1v), 0.0f);
        const float h11 = fmaxf(fmaf(x1, w1v, b1v), 0.0f);
        const float4* row = (const float4*)(sW2 + h * H_);
        #pragma unroll
        for (int k4 = 0; k4 < H_ / 4; k4++) {
            const float4 w = row[k4];
            acc0[k4 * 4 + 0] = fmaf(h10, w.x, acc0[k4 * 4 + 0]);
            acc0[k4 * 4 + 1] = fmaf(h10, w.y, acc0[k4 * 4 + 1]);
            acc0[k4 * 4 + 2] = fmaf(h10, w.z, acc0[k4 * 4 + 2]);
            acc0[k4 * 4 + 3] = fmaf(h10, w.w, acc0[k4 * 4 + 3]);
            acc1[k4 * 4 + 0] = fmaf(h11, w.x, acc1[k4 * 4 + 0]);
            acc1[k4 * 4 + 1] = fmaf(h11, w.y, acc1[k4 * 4 + 1]);
            acc1[k4 * 4 + 2] = fmaf(h11, w.z, acc1[k4 * 4 + 2]);
            acc1[k4 * 4 + 3] = fmaf(h11, w.w, acc1[k4 * 4 + 3]);
        }
    }

    // Output layer: relu(h2) . W3 + b3
    const float b3f = b3[f];
    float s0 = b3f, s1 = b3f;
    #pragma unroll
    for (int k = 0; k < H_; k++) {
        const float w3v = sW3[k];
        s0 = fmaf(fmaxf(acc0[k], 0.0f), w3v, s0);
        s1 = fmaf(fmaxf(acc1[k], 0.0f), w3v, s1);
    }

    if (v0) fnn[(size_t)r0 * F_ + f] = s0;
    if (v1) fnn[(size_t)r1 * F_ + f] = s1;
}

// out[b] = sum_f fnn[b, f]   (one warp per row; F_=128 -> 32 float4, one per lane)
__global__ __launch_bounds__(256) void nam_reduce_kernel(
    const float* __restrict__ fnn,
    float* __restrict__ out,
    int B)
{
    const int gwarp = (blockIdx.x * blockDim.x + threadIdx.x) >> 5;
    const int lane  = threadIdx.x & 31;
    if (gwarp >= B) return;
    const float4* row = (const float4*)(fnn + (size_t)gwarp * F_);
    const float4 v = row[lane];
    float s = (v.x + v.y) + (v.z + v.w);
    #pragma unroll
    for (int o = 16; o > 0; o >>= 1)
        s += __shfl_xor_sync(0xFFFFFFFFu, s, o);
    if (lane == 0) out[gwarp] = s;
}

extern "C" void kernel_launch(void* const* d_in, const int* in_sizes, int n_in,
                              void* d_out, int out_size)
{
    const float* inputs = (const float*)d_in[0];
    const float* W1     = (const float*)d_in[1];
    const float* b1     = (const float*)d_in[2];
    const float* W2     = (const float*)d_in[3];
    const float* b2     = (const float*)d_in[4];
    const float* W3     = (const float*)d_in[5];
    const float* b3     = (const float*)d_in[6];

    const int B = in_sizes[0] / F_;   // inputs is (B, F)

    float* out = (float*)d_out;       // first B elements: additive output
    float* fnn = out + B;             // next B*F elements: per-feature outputs

    dim3 grid1((B + BT - 1) / BT, F_);
    nam_main_kernel<<<grid1, TPB>>>(inputs, W1, b1, W2, b2, W3, b3, fnn, B);

    const int rb_threads = 256;                         // 8 warps/block
    const int rb_blocks  = (B * 32 + rb_threads - 1) / rb_threads;
    nam_reduce_kernel<<<rb_blocks, rb_threads>>>(fnn, out, B);
}

// round 5
// speedup vs baseline: 2.7596x; 2.7596x over previous
#include <cuda_runtime.h>
#include <cstdint>

// NAM via warp-level tf32 mma.sync (tcgen05 unavailable: PTX target is sm_103 non-a).
// inputs (B,F), W1/b1 (F,H), W2 (F,H,H), b2 (F,H), W3 (F,H), b3 (F)
// d_out = [ out (B) | fnn (B,F) ]

#define F_  128
#define H_  64
#define TILE_M 128
#define TPB 256          // 8 warps, one 16-row m-tile each
#define TILES_PER_CTA 8
#define MAX_B 16384

// scratch: fnn transposed (F, B) for cheap stores from the MMA kernel
__device__ float g_fnnT[(size_t)F_ * MAX_B];

__device__ __forceinline__ uint32_t to_tf32(float x) {
    uint32_t u;
    asm("cvt.rna.tf32.f32 %0, %1;" : "=r"(u) : "f"(x));
    return u;
}

__device__ __forceinline__ void mma_tf32(float d[4], const uint32_t a[4],
                                         uint32_t b0, uint32_t b1) {
    asm volatile(
        "mma.sync.aligned.m16n8k8.row.col.f32.tf32.tf32.f32 "
        "{%0,%1,%2,%3}, {%4,%5,%6,%7}, {%8,%9}, {%0,%1,%2,%3};"
        : "+f"(d[0]), "+f"(d[1]), "+f"(d[2]), "+f"(d[3])
        : "r"(a[0]), "r"(a[1]), "r"(a[2]), "r"(a[3]), "r"(b0), "r"(b1));
}

// smem: W2 fragment-order buffer + raw staging + x tile
__global__ __launch_bounds__(TPB) void nam_mma_kernel(
    const float* __restrict__ inputs,
    const float* __restrict__ W1, const float* __restrict__ b1,
    const float* __restrict__ W2, const float* __restrict__ b2,
    const float* __restrict__ W3, const float* __restrict__ b3,
    int B)
{
    // sBfrag[(j*4 + sp)*32 + lane] = uint4{ b0(s=2sp), b1(2sp), b0(2sp+1), b1(2sp+1) }
    //   where for n-tile j, k-step s: b0 = W2[k = s*8 + c][n = j*8 + g], b1 = same k+4
    //   (c = lane&3, g = lane>>2)
    __shared__ uint4  sBfrag[8 * 4 * 32];     // 16 KB
    __shared__ float  sW2raw[H_ * H_];        // 16 KB staging
    __shared__ float  sx[TILE_M];             // 512 B

    const int t    = threadIdx.x;
    const int wid  = t >> 5;
    const int lane = t & 31;
    const int c    = lane & 3;
    const int g    = lane >> 2;
    const int f    = blockIdx.y;
    const int cta_base = blockIdx.x * (TILE_M * TILES_PER_CTA);

    // ---- stage W2[f] coalesced, then scatter into fragment order ----
    {
        const float4* gW2 = (const float4*)(W2 + (size_t)f * H_ * H_);
        float4* sr = (float4*)sW2raw;
        #pragma unroll
        for (int i = 0; i < (H_ * H_ / 4) / TPB; i++)     // 4 iters
            sr[t + i * TPB] = gW2[t + i * TPB];
    }
    __syncthreads();
    {
        uint32_t* dst = (uint32_t*)sBfrag;
        #pragma unroll
        for (int i = 0; i < (8 * 4 * 32 * 4) / TPB; i++) { // 16 iters
            int idx = t + i * TPB;
            int q    = idx & 3;
            int ln   = (idx >> 2) & 31;
            int sp   = (idx >> 7) & 3;
            int j    = idx >> 9;
            int s    = 2 * sp + (q >> 1);
            int p    = q & 1;
            int k    = s * 8 + (ln & 3) + 4 * p;
            int n    = j * 8 + (ln >> 2);
            dst[idx] = to_tf32(sW2raw[k * H_ + n]);
        }
    }

    // ---- per-lane fragment constants for W1/b1 (A-prep) and W3/b2 (epilogue) ----
    uint32_t dummy; (void)dummy;
    float w1r[8][2], b1r[8][2], w3r[8][2], b2r[8][2];
    {
        const float* W1f = W1 + f * H_;
        const float* b1f = b1 + f * H_;
        const float* W3f = W3 + f * H_;
        const float* b2f = b2 + f * H_;
        #pragma unroll
        for (int s = 0; s < 8; s++) {
            w1r[s][0] = W1f[s * 8 + c];      b1r[s][0] = b1f[s * 8 + c];
            w1r[s][1] = W1f[s * 8 + c + 4];  b1r[s][1] = b1f[s * 8 + c + 4];
        }
        #pragma unroll
        for (int j = 0; j < 8; j++) {
            w3r[j][0] = W3f[j * 8 + 2 * c];     b2r[j][0] = b2f[j * 8 + 2 * c];
            w3r[j][1] = W3f[j * 8 + 2 * c + 1]; b2r[j][1] = b2f[j * 8 + 2 * c + 1];
        }
    }
    const float b3f = b3[f];
    __syncthreads();   // sBfrag ready

    for (int ti = 0; ti < TILES_PER_CTA; ti++) {
        const int tile_base = cta_base + ti * TILE_M;
        if (tile_base >= B) break;

        // load this tile's x column (threads 0..127)
        if (t < TILE_M) {
            int r = tile_base + t;
            sx[t] = (r < B) ? inputs[(size_t)r * F_ + f] : 0.0f;
        }
        __syncthreads();

        const int m0 = wid * 16;            // warp's rows within tile
        const float x0 = sx[m0 + g];
        const float x1 = sx[m0 + 8 + g];

        // A fragments: h1 = relu(x*W1 + b1), tf32-rounded
        uint32_t a[8][4];
        #pragma unroll
        for (int s = 0; s < 8; s++) {
            a[s][0] = to_tf32(fmaxf(fmaf(x0, w1r[s][0], b1r[s][0]), 0.0f));
            a[s][1] = to_tf32(fmaxf(fmaf(x1, w1r[s][0], b1r[s][0]), 0.0f));
            a[s][2] = to_tf32(fmaxf(fmaf(x0, w1r[s][1], b1r[s][1]), 0.0f));
            a[s][3] = to_tf32(fmaxf(fmaf(x1, w1r[s][1], b1r[s][1]), 0.0f));
        }

        // D = A @ W2[f]  (8 n-tiles x 8 k-steps)
        float d[8][4];
        #pragma unroll
        for (int j = 0; j < 8; j++) {
            d[j][0] = 0.f; d[j][1] = 0.f; d[j][2] = 0.f; d[j][3] = 0.f;
        }
        #pragma unroll
        for (int j = 0; j < 8; j++) {
            #pragma unroll
            for (int sp = 0; sp < 4; sp++) {
                const uint4 bv = sBfrag[(j * 4 + sp) * 32 + lane];
                mma_tf32(d[j], a[2 * sp],     bv.x, bv.y);
                mma_tf32(d[j], a[2 * sp + 1], bv.z, bv.w);
            }
        }

        // epilogue: fnn = relu(D + b2) . W3 + b3
        float s0 = 0.f, s1 = 0.f;
        #pragma unroll
        for (int j = 0; j < 8; j++) {
            s0 = fmaf(fmaxf(d[j][0] + b2r[j][0], 0.f), w3r[j][0], s0);
            s0 = fmaf(fmaxf(d[j][1] + b2r[j][1], 0.f), w3r[j][1], s0);
            s1 = fmaf(fmaxf(d[j][2] + b2r[j][0], 0.f), w3r[j][0], s1);
            s1 = fmaf(fmaxf(d[j][3] + b2r[j][1], 0.f), w3r[j][1], s1);
        }
        s0 += __shfl_xor_sync(0xFFFFFFFFu, s0, 1);
        s0 += __shfl_xor_sync(0xFFFFFFFFu, s0, 2);
        s1 += __shfl_xor_sync(0xFFFFFFFFu, s1, 1);
        s1 += __shfl_xor_sync(0xFFFFFFFFu, s1, 2);

        if (c == 0) {
            const int r0 = tile_base + m0 + g;
            const int r1 = r0 + 8;
            if (r0 < B) g_fnnT[(size_t)f * B + r0] = s0 + b3f;
            if (r1 < B) g_fnnT[(size_t)f * B + r1] = s1 + b3f;
        }
        __syncthreads();   // before next tile overwrites sx
    }
}

// transpose fnnT -> fnn (B,F) and out[b] = sum_f fnn[b,f]
__global__ __launch_bounds__(128) void nam_finish_kernel(
    float* __restrict__ out, float* __restrict__ fnn, int B)
{
    __shared__ float s[F_][33];
    const int b0 = blockIdx.x * 32;
    const int t = threadIdx.x;
    const int bb = t & 31, fo = t >> 5;

    #pragma unroll
    for (int fi = fo; fi < F_; fi += 4)
        s[fi][bb] = (b0 + bb < B) ? g_fnnT[(size_t)fi * B + b0 + bb] : 0.0f;
    __syncthreads();

    for (int i = t; i < 32 * F_; i += 128) {
        int b = i >> 7, fc = i & 127;
        if (b0 + b < B) fnn[(size_t)(b0 + b) * F_ + fc] = s[fc][b];
    }
    if (t < 32 && b0 + t < B) {
        float acc = 0.0f;
        #pragma unroll 8
        for (int fc = 0; fc < F_; fc++) acc += s[fc][t];
        out[b0 + t] = acc;
    }
}

extern "C" void kernel_launch(void* const* d_in, const int* in_sizes, int n_in,
                              void* d_out, int out_size)
{
    const float* inputs = (const float*)d_in[0];
    const float* W1     = (const float*)d_in[1];
    const float* b1     = (const float*)d_in[2];
    const float* W2     = (const float*)d_in[3];
    const float* b2     = (const float*)d_in[4];
    const float* W3     = (const float*)d_in[5];
    const float* b3     = (const float*)d_in[6];

    const int B = in_sizes[0] / F_;
    float* out = (float*)d_out;
    float* fnn = out + B;

    dim3 grid((B + TILE_M * TILES_PER_CTA - 1) / (TILE_M * TILES_PER_CTA), F_);
    nam_mma_kernel<<<grid, TPB>>>(inputs, W1, b1, W2, b2, W3, b3, B);

    nam_finish_kernel<<<(B + 31) / 32, 128>>>(out, fnn, B);
}